// round 5
// baseline (speedup 1.0000x reference)
#include <cuda_runtime.h>
#include <math.h>

#define BATCH 16
#define NCLS 90
#define NSEL 5000
#define CAPC 262144
#define THRESH0 2.0f
#define NDET 100

// ---------------- static device scratch (no allocations allowed) ----------------
static __device__ unsigned g_cand_cnt[BATCH];
static __device__ float    g_cand_val[BATCH * CAPC];
static __device__ unsigned g_cand_idx[BATCH * CAPC];

static __device__ float g_nb0[BATCH * NSEL];   // class-offset boxes (reference 'nb')
static __device__ float g_nb1[BATCH * NSEL];
static __device__ float g_nb2[BATCH * NSEL];
static __device__ float g_nb3[BATCH * NSEL];
static __device__ float g_ob0[BATCH * NSEL];   // original decoded boxes (for output)
static __device__ float g_ob1[BATCH * NSEL];
static __device__ float g_ob2[BATCH * NSEL];
static __device__ float g_ob3[BATCH * NSEL];
static __device__ float g_area[BATCH * NSEL];  // area of nb (reference exact)
static __device__ float g_score[BATCH * NSEL]; // sigmoid for output
static __device__ float g_val[BATCH * NSEL];   // raw logit (ordering key)
static __device__ unsigned g_clsid[BATCH * NSEL];
static __device__ unsigned g_flat[BATCH * NSEL];
static __device__ int g_sel_total[BATCH];
static __device__ int g_cls_cnt[BATCH * NCLS];
static __device__ int g_cls_off[BATCH * (NCLS + 1)];
static __device__ int g_order[BATCH * NSEL];
static __device__ unsigned long long g_surv_key[BATCH * NSEL];
static __device__ unsigned g_surv_slot[BATCH * NSEL];
static __device__ unsigned g_surv_cnt[BATCH];

// ---------------- init ----------------
__global__ void k_init() {
    int t = blockIdx.x * blockDim.x + threadIdx.x;
    if (t < BATCH) { g_cand_cnt[t] = 0; g_surv_cnt[t] = 0; g_sel_total[t] = 0; }
    if (t < BATCH * NCLS) g_cls_cnt[t] = 0;
}

// ---------------- pass 1: threshold compaction of cls logits ----------------
// cls_out level layout [B, 9*90, hw, hw]; element e within image:
//   ch = e / hw2, pix = e % hw2, a = ch/90, c = ch%90
//   flat = (lvl_off + pix*9 + a)*90 + c
// Ballot is safe: NOT inside a variable-trip loop; all lanes reach it.
__global__ void k_compact(const float* __restrict__ cls, int hw2, int lvl_off, int elems) {
    int b = blockIdx.y;
    int base = (blockIdx.x * blockDim.x + threadIdx.x) * 4;
    bool inb = base < elems;
    float4 v = make_float4(0.f, 0.f, 0.f, 0.f);
    if (inb) v = *reinterpret_cast<const float4*>(cls + (size_t)b * elems + base);
    float vv[4] = {v.x, v.y, v.z, v.w};
    int lane = threadIdx.x & 31;
#pragma unroll
    for (int j = 0; j < 4; j++) {
        bool p = inb && (vv[j] > THRESH0);
        unsigned m = __ballot_sync(0xffffffffu, p);
        if (m) {
            int leader = __ffs(m) - 1;
            unsigned pos0 = 0;
            if (lane == leader) pos0 = atomicAdd(&g_cand_cnt[b], (unsigned)__popc(m));
            pos0 = __shfl_sync(0xffffffffu, pos0, leader);
            if (p) {
                unsigned pos = pos0 + __popc(m & ((1u << lane) - 1u));
                if (pos < CAPC) {
                    int e = base + j;
                    int ch = e / hw2;
                    int pix = e - ch * hw2;
                    int a = ch / NCLS;
                    int c = ch - a * NCLS;
                    unsigned flat = (unsigned)(lvl_off + pix * 9 + a) * NCLS + c;
                    g_cand_val[b * CAPC + pos] = vv[j];
                    g_cand_idx[b * CAPC + pos] = flat;
                }
            }
        }
    }
}

// ---------------- decode + store one selected detection ----------------
__device__ __forceinline__ void decode_store(
    int b, int pos, float v, unsigned flat,
    const float* bx0, const float* bx1, const float* bx2,
    const float* bx3, const float* bx4,
    const float* __restrict__ anchors, int* s_scnt)
{
    unsigned anchor = flat / NCLS;
    unsigned c = flat - anchor * NCLS;
    int li, off, hw2;
    if (anchor < 36864u)      { li = 0; off = 0;     hw2 = 4096; }
    else if (anchor < 46080u) { li = 1; off = 36864; hw2 = 1024; }
    else if (anchor < 48384u) { li = 2; off = 46080; hw2 = 256; }
    else if (anchor < 48960u) { li = 3; off = 48384; hw2 = 64; }
    else                      { li = 4; off = 48960; hw2 = 16; }
    const float* bp = (li == 0) ? bx0 : (li == 1) ? bx1 : (li == 2) ? bx2 : (li == 3) ? bx3 : bx4;
    unsigned ai = anchor - off;
    unsigned cell = ai / 9u;
    unsigned a = ai - cell * 9u;
    size_t ib = (size_t)b * 36 * hw2 + (size_t)(a * 4) * hw2 + cell;
    float ty = __ldg(bp + ib);
    float tx = __ldg(bp + ib + hw2);
    float th = __ldg(bp + ib + 2 * hw2);
    float tw = __ldg(bp + ib + 3 * hw2);
    float4 an = __ldg(reinterpret_cast<const float4*>(anchors) + anchor);
    float ya = (an.x + an.z) * 0.5f;
    float xa = (an.y + an.w) * 0.5f;
    float ha = an.z - an.x;
    float wa = an.w - an.y;
    float h = expf(th) * ha;
    float w = expf(tw) * wa;
    float yc = ty * ha + ya;
    float xc = tx * wa + xa;
    float y1 = yc - h * 0.5f, x1 = xc - w * 0.5f;
    float y2 = yc + h * 0.5f, x2 = xc + w * 0.5f;
    // reference: nb = boxes + class*10000  (area & IoU computed on nb — replicate rounding!)
    float offc = (float)c * 10000.0f;
    float n0 = y1 + offc, n1 = x1 + offc, n2 = y2 + offc, n3 = x2 + offc;
    int o = b * NSEL + pos;
    g_ob0[o] = y1; g_ob1[o] = x1; g_ob2[o] = y2; g_ob3[o] = x2;
    g_nb0[o] = n0; g_nb1[o] = n1; g_nb2[o] = n2; g_nb3[o] = n3;
    g_area[o] = (n2 - n0) * (n3 - n1);
    g_score[o] = 1.0f / (1.0f + expf(-v));
    g_val[o] = v;
    g_clsid[o] = c;
    g_flat[o] = flat;
    atomicAdd(&s_scnt[c], 1);
}

// ---------------- pass 2: exact top-5000 via radix select over candidates ----------------
// Plain shared atomics only — no warp collectives inside variable-trip loops.
__global__ void k_select(const float* bx0, const float* bx1, const float* bx2,
                         const float* bx3, const float* bx4, const float* anchors)
{
    int b = blockIdx.x;
    int tid = threadIdx.x;
    __shared__ unsigned s_cnt[256];
    __shared__ unsigned s_prefix;
    __shared__ int s_k;
    __shared__ int s_scnt[NCLS];
    __shared__ unsigned s_seln, s_eqn;
    __shared__ unsigned s_eq[1024];

    unsigned n = min(g_cand_cnt[b], (unsigned)CAPC);
    const float* cv = g_cand_val + (size_t)b * CAPC;
    const unsigned* ci = g_cand_idx + (size_t)b * CAPC;

    if (tid == 0) { s_prefix = 0; s_k = (int)min((unsigned)NSEL, n); }
    for (int r = 0; r < 4; r++) {
        int shift = 24 - 8 * r;
        unsigned hmask = (r == 0) ? 0u : (0xFFFFFFFFu << (shift + 8));
        __syncthreads();
        if (tid < 256) s_cnt[tid] = 0;
        __syncthreads();
        unsigned pref = s_prefix;
        for (unsigned i = tid; i < n; i += blockDim.x) {
            unsigned u = __float_as_uint(cv[i]);
            if ((u & hmask) == pref)
                atomicAdd(&s_cnt[(u >> shift) & 255u], 1u);
        }
        __syncthreads();
        if (tid == 0) {
            int k = s_k;
            unsigned cum = 0;
            int sel = 0;
            for (int x = 255; x >= 0; x--) {
                cum += s_cnt[x];
                if ((int)cum >= k) { sel = x; s_k = k - (int)(cum - s_cnt[x]); break; }
            }
            s_prefix = pref | ((unsigned)sel << shift);
        }
    }
    __syncthreads();
    unsigned K = s_prefix;
    int rrem = s_k;
    if (tid == 0) { s_seln = 0; s_eqn = 0; }
    if (tid < NCLS) s_scnt[tid] = 0;
    __syncthreads();
    for (unsigned i = tid; i < n; i += blockDim.x) {
        unsigned u = __float_as_uint(cv[i]);
        if (u > K) {
            unsigned pos = atomicAdd(&s_seln, 1u);
            if (pos < NSEL)
                decode_store(b, (int)pos, cv[i], ci[i], bx0, bx1, bx2, bx3, bx4, anchors, s_scnt);
        } else if (u == K) {
            unsigned e = atomicAdd(&s_eqn, 1u);
            if (e < 1024u) s_eq[e] = i;
        }
    }
    __syncthreads();
    if (tid == 0) {
        unsigned base = min(s_seln, (unsigned)NSEL);
        unsigned ne = min(s_eqn, 1024u);
        unsigned r = (rrem > 0) ? (unsigned)rrem : 0u;
        if (r > ne) r = ne;
        bool used[1024];
        for (unsigned j = 0; j < ne; j++) used[j] = false;
        unsigned placed = 0;
        for (unsigned t = 0; t < r && base + t < NSEL; t++) {
            unsigned bestf = 0xFFFFFFFFu; int bj = -1;
            for (unsigned j = 0; j < ne; j++) {
                if (!used[j]) { unsigned f = ci[s_eq[j]]; if (f < bestf) { bestf = f; bj = (int)j; } }
            }
            if (bj < 0) break;
            used[bj] = true;
            unsigned idx = s_eq[bj];
            decode_store(b, (int)(base + t), cv[idx], ci[idx], bx0, bx1, bx2, bx3, bx4, anchors, s_scnt);
            placed++;
        }
        unsigned tot = base + placed;
        g_sel_total[b] = (int)((tot > NSEL) ? NSEL : tot);
    }
    __syncthreads();
    if (tid < NCLS) g_cls_cnt[b * NCLS + tid] = s_scnt[tid];
}

// ---------------- pass 3: bucket by class ----------------
__global__ void k_bucket() {
    int b = blockIdx.x;
    int tid = threadIdx.x;
    __shared__ int off[NCLS + 1];
    __shared__ int fill[NCLS];
    if (tid == 0) {
        off[0] = 0;
        for (int c = 0; c < NCLS; c++) off[c + 1] = off[c] + g_cls_cnt[b * NCLS + c];
    }
    __syncthreads();
    if (tid < NCLS + 1) g_cls_off[b * (NCLS + 1) + tid] = off[tid];
    if (tid < NCLS) fill[tid] = off[tid];
    __syncthreads();
    int tot = g_sel_total[b];
    for (int i = tid; i < tot; i += blockDim.x) {
        int c = (int)g_clsid[b * NSEL + i];
        int pos = atomicAdd(&fill[c], 1);
        g_order[b * NSEL + pos] = i;
    }
}

// ---------------- bitonic sort (descending), key + payload ----------------
__device__ __forceinline__ void bitonic_desc(unsigned long long* skey, unsigned* sslot, int NP) {
    for (int k = 2; k <= NP; k <<= 1) {
        for (int j = k >> 1; j > 0; j >>= 1) {
            for (int i = threadIdx.x; i < NP; i += blockDim.x) {
                int l = i ^ j;
                if (l > i) {
                    bool d = ((i & k) == 0);
                    unsigned long long a = skey[i], e = skey[l];
                    bool sw = d ? (a < e) : (a > e);
                    if (sw) {
                        skey[i] = e; skey[l] = a;
                        unsigned t = sslot[i]; sslot[i] = sslot[l]; sslot[l] = t;
                    }
                }
            }
            __syncthreads();
        }
    }
}

// ---------------- pass 4: per-(image,class) greedy NMS ----------------
__global__ void k_nms(int lo, int hi) {
    int b = blockIdx.y, c = blockIdx.x;
    int start = g_cls_off[b * (NCLS + 1) + c];
    int n = g_cls_off[b * (NCLS + 1) + c + 1] - start;
    if (n <= 0 || n <= lo || n > hi) return;

    int NP = 128;
    while (NP < n) NP <<= 1;

    extern __shared__ unsigned long long sm64[];
    unsigned long long* skey = sm64;
    unsigned* sslot = (unsigned*)(skey + NP);
    unsigned char* supp = (unsigned char*)(sslot + NP);
    __shared__ float bb[5];

    for (int i = threadIdx.x; i < NP; i += blockDim.x) {
        if (i < n) {
            int item = g_order[b * NSEL + start + i];
            unsigned vb = __float_as_uint(g_val[b * NSEL + item]);
            unsigned fl = g_flat[b * NSEL + item];
            skey[i] = ((unsigned long long)vb << 32) | (unsigned long long)(~fl);
            sslot[i] = (unsigned)item;
        } else {
            skey[i] = 0ull;
            sslot[i] = 0u;
        }
        supp[i] = 0;
    }
    __syncthreads();
    bitonic_desc(skey, sslot, NP);

    for (int i = 0; i < n; i++) {
        __syncthreads();
        if (supp[i]) continue;   // uniform branch: supp is shared
        if (threadIdx.x == 0) {
            unsigned pos = atomicAdd(&g_surv_cnt[b], 1u);
            if (pos < NSEL) {
                g_surv_key[b * NSEL + pos] = skey[i];
                g_surv_slot[b * NSEL + pos] = sslot[i];
            }
            int o = b * NSEL + (int)sslot[i];
            bb[0] = g_nb0[o]; bb[1] = g_nb1[o]; bb[2] = g_nb2[o]; bb[3] = g_nb3[o]; bb[4] = g_area[o];
        }
        __syncthreads();
        float b0 = bb[0], b1 = bb[1], b2 = bb[2], b3 = bb[3], ba = bb[4];
        for (int j = i + 1 + threadIdx.x; j < n; j += blockDim.x) {
            if (!supp[j]) {
                int o = b * NSEL + (int)sslot[j];
                float yy1 = fmaxf(g_nb0[o], b0);
                float xx1 = fmaxf(g_nb1[o], b1);
                float yy2 = fminf(g_nb2[o], b2);
                float xx2 = fminf(g_nb3[o], b3);
                float ih = fmaxf(yy2 - yy1, 0.0f);
                float iw = fmaxf(xx2 - xx1, 0.0f);
                float inter = ih * iw;
                float iou = inter / (g_area[o] + ba - inter + 1e-8f);
                if (iou > 0.5f) supp[j] = 1;
            }
        }
    }
}

// ---------------- pass 5: global sort of survivors + emit top-100 ----------------
__global__ void k_final(const float* __restrict__ scales, float* __restrict__ out) {
    int b = blockIdx.x;
    int tid = threadIdx.x;
    unsigned cnt = min(g_surv_cnt[b], (unsigned)NSEL);
    int NP = 256;
    while (NP < (int)cnt) NP <<= 1;

    extern __shared__ unsigned long long sm64[];
    unsigned long long* skey = sm64;
    unsigned* sslot = (unsigned*)(skey + NP);

    for (int i = tid; i < NP; i += blockDim.x) {
        if (i < (int)cnt) {
            skey[i] = g_surv_key[b * NSEL + i];
            sslot[i] = g_surv_slot[b * NSEL + i];
        } else {
            skey[i] = 0ull;
            sslot[i] = 0u;
        }
    }
    __syncthreads();
    bitonic_desc(skey, sslot, NP);

    if (tid < NDET) {
        float row[6] = {0.f, 0.f, 0.f, 0.f, 0.f, 0.f};
        if (tid < (int)cnt) {
            int o = b * NSEL + (int)sslot[tid];
            float sc = scales[b];
            row[0] = g_ob0[o] * sc;
            row[1] = g_ob1[o] * sc;
            row[2] = g_ob2[o] * sc;
            row[3] = g_ob3[o] * sc;
            row[4] = g_score[o];
            row[5] = (float)(g_clsid[o] + 1u);
        }
#pragma unroll
        for (int j = 0; j < 6; j++) out[b * (NDET * 6) + tid * 6 + j] = row[j];
    }
}

// ---------------- host ----------------
extern "C" void kernel_launch(void* const* d_in, const int* in_sizes, int n_in,
                              void* d_out, int out_size) {
    // Identify inputs BY ELEMENT COUNT (all 12 counts are unique) — robust to
    // any metadata ordering (setup_inputs interleaves cls/box per level).
    static const long long CLSN[5] = {53084160LL, 13271040LL, 3317760LL, 829440LL, 207360LL};
    static const long long BOXN[5] = {2359296LL, 589824LL, 147456LL, 36864LL, 9216LL};
    const float* cls[5] = {0, 0, 0, 0, 0};
    const float* box[5] = {0, 0, 0, 0, 0};
    const float* anchors = 0;
    const float* scales = 0;
    for (int i = 0; i < n_in; i++) {
        long long s = in_sizes[i];
        const float* p = (const float*)d_in[i];
        for (int l = 0; l < 5; l++) {
            if (s == CLSN[l]) cls[l] = p;
            if (s == BOXN[l]) box[l] = p;
        }
        if (s == 196416LL) anchors = p;
        if (s == 16LL) scales = p;
    }
    float* out = (float*)d_out;

    const int NMS_BIG_SM = 8192 * 13 + 128;   // 8192*(8+4+1)
    const int NMS_SMALL_SM = 512 * 13 + 128;
    const int FIN_SM = 8192 * 12;
    cudaFuncSetAttribute(k_nms, cudaFuncAttributeMaxDynamicSharedMemorySize, NMS_BIG_SM);
    cudaFuncSetAttribute(k_final, cudaFuncAttributeMaxDynamicSharedMemorySize, FIN_SM);

    k_init<<<dim3((BATCH * NCLS + 255) / 256), 256>>>();

    const int HW2[5] = {4096, 1024, 256, 64, 16};
    const int OFF[5] = {0, 36864, 46080, 48384, 48960};
    for (int li = 0; li < 5; li++) {
        int elems = 810 * HW2[li];
        int gx = (elems + 1023) / 1024;  // 256 threads * 4 floats
        k_compact<<<dim3(gx, BATCH), 256>>>(cls[li], HW2[li], OFF[li], elems);
    }

    k_select<<<BATCH, 1024>>>(box[0], box[1], box[2], box[3], box[4], anchors);
    k_bucket<<<BATCH, 128>>>();
    k_nms<<<dim3(NCLS, BATCH), 128, NMS_SMALL_SM>>>(0, 512);
    k_nms<<<dim3(NCLS, BATCH), 128, NMS_BIG_SM>>>(512, NSEL);
    k_final<<<BATCH, 256, FIN_SM>>>(scales, out);
}

// round 10
// speedup vs baseline: 1.9046x; 1.9046x over previous
#include <cuda_runtime.h>
#include <math.h>

#define BATCH 16
#define NCLS 90
#define NSEL 5000
#define CAPC 262144
#define THRESH0 2.0f
#define NDET 100

// ---------------- static device scratch (no allocations allowed) ----------------
static __device__ unsigned g_cand_cnt[BATCH];
static __device__ float    g_cand_val[BATCH * CAPC];
static __device__ unsigned g_cand_idx[BATCH * CAPC];

static __device__ float g_nb0[BATCH * NSEL];   // class-offset boxes (reference 'nb')
static __device__ float g_nb1[BATCH * NSEL];
static __device__ float g_nb2[BATCH * NSEL];
static __device__ float g_nb3[BATCH * NSEL];
static __device__ float g_ob0[BATCH * NSEL];   // original decoded boxes (for output)
static __device__ float g_ob1[BATCH * NSEL];
static __device__ float g_ob2[BATCH * NSEL];
static __device__ float g_ob3[BATCH * NSEL];
static __device__ float g_area[BATCH * NSEL];  // area of nb (reference exact)
static __device__ float g_score[BATCH * NSEL]; // sigmoid for output
static __device__ float g_val[BATCH * NSEL];   // raw logit (ordering key)
static __device__ unsigned g_clsid[BATCH * NSEL];
static __device__ unsigned g_flat[BATCH * NSEL];
static __device__ int g_sel_total[BATCH];
static __device__ int g_cls_cnt[BATCH * NCLS];
static __device__ int g_cls_off[BATCH * (NCLS + 1)];
static __device__ int g_order[BATCH * NSEL];
static __device__ unsigned long long g_surv_key[BATCH * NSEL];
static __device__ unsigned g_surv_slot[BATCH * NSEL];
static __device__ unsigned g_surv_cnt[BATCH];

// ---------------- init ----------------
__global__ void k_init() {
    int t = blockIdx.x * blockDim.x + threadIdx.x;
    if (t < BATCH) { g_cand_cnt[t] = 0; g_surv_cnt[t] = 0; g_sel_total[t] = 0; }
    if (t < BATCH * NCLS) g_cls_cnt[t] = 0;
}

// ---------------- pass 1: threshold compaction of cls logits ----------------
// cls_out level layout [B, 9*90, hw, hw]; element e within image:
//   ch = e / hw2, pix = e % hw2, a = ch/90, c = ch%90
//   flat = (lvl_off + pix*9 + a)*90 + c
// ONE global atomicAdd per BLOCK (R5 fix: per-warp atomics onto 16 addresses
// were the entire 1.3ms). Block total via 4 ballots + 8-warp shared scan;
// threads place candidates at block_base + warp_base + intra-warp rank.
// Buffer order changes; selection is order-agnostic (ties broken by flat idx).
__global__ void k_compact(const float* __restrict__ cls, int hw2, int lvl_off, int elems) {
    int b = blockIdx.y;
    int tid = threadIdx.x;
    int wid = tid >> 5, lane = tid & 31;
    int base = (blockIdx.x * blockDim.x + tid) * 4;
    bool inb = base < elems;
    float4 v = make_float4(-10.f, -10.f, -10.f, -10.f);
    if (inb) v = *reinterpret_cast<const float4*>(cls + (size_t)b * elems + base);
    float vv[4] = {v.x, v.y, v.z, v.w};

    unsigned m[4];
#pragma unroll
    for (int j = 0; j < 4; j++)
        m[j] = __ballot_sync(0xffffffffu, vv[j] > THRESH0);

    int wtot = __popc(m[0]) + __popc(m[1]) + __popc(m[2]) + __popc(m[3]);

    __shared__ int s_w[8];
    __shared__ unsigned s_base;
    if (lane == 0) s_w[wid] = wtot;
    __syncthreads();
    if (tid == 0) {
        int tot = 0;
#pragma unroll
        for (int w = 0; w < 8; w++) { int t = s_w[w]; s_w[w] = tot; tot += t; }
        s_base = tot ? atomicAdd(&g_cand_cnt[b], (unsigned)tot) : 0u;
    }
    __syncthreads();
    if (wtot == 0) return;

    unsigned wbase = s_base + (unsigned)s_w[wid];
    unsigned lmask = (1u << lane) - 1u;
    int pre = 0;
#pragma unroll
    for (int j = 0; j < 4; j++) {
        if ((m[j] >> lane) & 1u) {
            unsigned pos = wbase + (unsigned)(pre + __popc(m[j] & lmask));
            if (pos < CAPC) {
                int e = base + j;
                int ch = e / hw2;
                int pix = e - ch * hw2;
                int a = ch / NCLS;
                int c = ch - a * NCLS;
                unsigned flat = (unsigned)(lvl_off + pix * 9 + a) * NCLS + c;
                g_cand_val[b * CAPC + pos] = vv[j];
                g_cand_idx[b * CAPC + pos] = flat;
            }
        }
        pre += __popc(m[j]);
    }
}

// ---------------- decode + store one selected detection ----------------
__device__ __forceinline__ void decode_store(
    int b, int pos, float v, unsigned flat,
    const float* bx0, const float* bx1, const float* bx2,
    const float* bx3, const float* bx4,
    const float* __restrict__ anchors, int* s_scnt)
{
    unsigned anchor = flat / NCLS;
    unsigned c = flat - anchor * NCLS;
    int li, off, hw2;
    if (anchor < 36864u)      { li = 0; off = 0;     hw2 = 4096; }
    else if (anchor < 46080u) { li = 1; off = 36864; hw2 = 1024; }
    else if (anchor < 48384u) { li = 2; off = 46080; hw2 = 256; }
    else if (anchor < 48960u) { li = 3; off = 48384; hw2 = 64; }
    else                      { li = 4; off = 48960; hw2 = 16; }
    const float* bp = (li == 0) ? bx0 : (li == 1) ? bx1 : (li == 2) ? bx2 : (li == 3) ? bx3 : bx4;
    unsigned ai = anchor - off;
    unsigned cell = ai / 9u;
    unsigned a = ai - cell * 9u;
    size_t ib = (size_t)b * 36 * hw2 + (size_t)(a * 4) * hw2 + cell;
    float ty = __ldg(bp + ib);
    float tx = __ldg(bp + ib + hw2);
    float th = __ldg(bp + ib + 2 * hw2);
    float tw = __ldg(bp + ib + 3 * hw2);
    float4 an = __ldg(reinterpret_cast<const float4*>(anchors) + anchor);
    float ya = (an.x + an.z) * 0.5f;
    float xa = (an.y + an.w) * 0.5f;
    float ha = an.z - an.x;
    float wa = an.w - an.y;
    float h = expf(th) * ha;
    float w = expf(tw) * wa;
    float yc = ty * ha + ya;
    float xc = tx * wa + xa;
    float y1 = yc - h * 0.5f, x1 = xc - w * 0.5f;
    float y2 = yc + h * 0.5f, x2 = xc + w * 0.5f;
    // reference: nb = boxes + class*10000  (area & IoU computed on nb — replicate rounding!)
    float offc = (float)c * 10000.0f;
    float n0 = y1 + offc, n1 = x1 + offc, n2 = y2 + offc, n3 = x2 + offc;
    int o = b * NSEL + pos;
    g_ob0[o] = y1; g_ob1[o] = x1; g_ob2[o] = y2; g_ob3[o] = x2;
    g_nb0[o] = n0; g_nb1[o] = n1; g_nb2[o] = n2; g_nb3[o] = n3;
    g_area[o] = (n2 - n0) * (n3 - n1);
    g_score[o] = 1.0f / (1.0f + expf(-v));
    g_val[o] = v;
    g_clsid[o] = c;
    g_flat[o] = flat;
    atomicAdd(&s_scnt[c], 1);
}

// ---------------- pass 2: exact top-5000 via radix select over candidates ----------------
// Plain shared atomics only — no warp collectives inside variable-trip loops.
__global__ void k_select(const float* bx0, const float* bx1, const float* bx2,
                         const float* bx3, const float* bx4, const float* anchors)
{
    int b = blockIdx.x;
    int tid = threadIdx.x;
    __shared__ unsigned s_cnt[256];
    __shared__ unsigned s_prefix;
    __shared__ int s_k;
    __shared__ int s_scnt[NCLS];
    __shared__ unsigned s_seln, s_eqn;
    __shared__ unsigned s_eq[1024];

    unsigned n = min(g_cand_cnt[b], (unsigned)CAPC);
    const float* cv = g_cand_val + (size_t)b * CAPC;
    const unsigned* ci = g_cand_idx + (size_t)b * CAPC;

    if (tid == 0) { s_prefix = 0; s_k = (int)min((unsigned)NSEL, n); }
    for (int r = 0; r < 4; r++) {
        int shift = 24 - 8 * r;
        unsigned hmask = (r == 0) ? 0u : (0xFFFFFFFFu << (shift + 8));
        __syncthreads();
        if (tid < 256) s_cnt[tid] = 0;
        __syncthreads();
        unsigned pref = s_prefix;
        for (unsigned i = tid; i < n; i += blockDim.x) {
            unsigned u = __float_as_uint(cv[i]);
            if ((u & hmask) == pref)
                atomicAdd(&s_cnt[(u >> shift) & 255u], 1u);
        }
        __syncthreads();
        if (tid == 0) {
            int k = s_k;
            unsigned cum = 0;
            int sel = 0;
            for (int x = 255; x >= 0; x--) {
                cum += s_cnt[x];
                if ((int)cum >= k) { sel = x; s_k = k - (int)(cum - s_cnt[x]); break; }
            }
            s_prefix = pref | ((unsigned)sel << shift);
        }
    }
    __syncthreads();
    unsigned K = s_prefix;
    int rrem = s_k;
    if (tid == 0) { s_seln = 0; s_eqn = 0; }
    if (tid < NCLS) s_scnt[tid] = 0;
    __syncthreads();
    for (unsigned i = tid; i < n; i += blockDim.x) {
        unsigned u = __float_as_uint(cv[i]);
        if (u > K) {
            unsigned pos = atomicAdd(&s_seln, 1u);
            if (pos < NSEL)
                decode_store(b, (int)pos, cv[i], ci[i], bx0, bx1, bx2, bx3, bx4, anchors, s_scnt);
        } else if (u == K) {
            unsigned e = atomicAdd(&s_eqn, 1u);
            if (e < 1024u) s_eq[e] = i;
        }
    }
    __syncthreads();
    if (tid == 0) {
        unsigned base = min(s_seln, (unsigned)NSEL);
        unsigned ne = min(s_eqn, 1024u);
        unsigned r = (rrem > 0) ? (unsigned)rrem : 0u;
        if (r > ne) r = ne;
        bool used[1024];
        for (unsigned j = 0; j < ne; j++) used[j] = false;
        unsigned placed = 0;
        for (unsigned t = 0; t < r && base + t < NSEL; t++) {
            unsigned bestf = 0xFFFFFFFFu; int bj = -1;
            for (unsigned j = 0; j < ne; j++) {
                if (!used[j]) { unsigned f = ci[s_eq[j]]; if (f < bestf) { bestf = f; bj = (int)j; } }
            }
            if (bj < 0) break;
            used[bj] = true;
            unsigned idx = s_eq[bj];
            decode_store(b, (int)(base + t), cv[idx], ci[idx], bx0, bx1, bx2, bx3, bx4, anchors, s_scnt);
            placed++;
        }
        unsigned tot = base + placed;
        g_sel_total[b] = (int)((tot > NSEL) ? NSEL : tot);
    }
    __syncthreads();
    if (tid < NCLS) g_cls_cnt[b * NCLS + tid] = s_scnt[tid];
}

// ---------------- pass 3: bucket by class ----------------
__global__ void k_bucket() {
    int b = blockIdx.x;
    int tid = threadIdx.x;
    __shared__ int off[NCLS + 1];
    __shared__ int fill[NCLS];
    if (tid == 0) {
        off[0] = 0;
        for (int c = 0; c < NCLS; c++) off[c + 1] = off[c] + g_cls_cnt[b * NCLS + c];
    }
    __syncthreads();
    if (tid < NCLS + 1) g_cls_off[b * (NCLS + 1) + tid] = off[tid];
    if (tid < NCLS) fill[tid] = off[tid];
    __syncthreads();
    int tot = g_sel_total[b];
    for (int i = tid; i < tot; i += blockDim.x) {
        int c = (int)g_clsid[b * NSEL + i];
        int pos = atomicAdd(&fill[c], 1);
        g_order[b * NSEL + pos] = i;
    }
}

// ---------------- bitonic sort (descending), key + payload ----------------
__device__ __forceinline__ void bitonic_desc(unsigned long long* skey, unsigned* sslot, int NP) {
    for (int k = 2; k <= NP; k <<= 1) {
        for (int j = k >> 1; j > 0; j >>= 1) {
            for (int i = threadIdx.x; i < NP; i += blockDim.x) {
                int l = i ^ j;
                if (l > i) {
                    bool d = ((i & k) == 0);
                    unsigned long long a = skey[i], e = skey[l];
                    bool sw = d ? (a < e) : (a > e);
                    if (sw) {
                        skey[i] = e; skey[l] = a;
                        unsigned t = sslot[i]; sslot[i] = sslot[l]; sslot[l] = t;
                    }
                }
            }
            __syncthreads();
        }
    }
}

// ---------------- pass 4: per-(image,class) greedy NMS ----------------
__global__ void k_nms(int lo, int hi) {
    int b = blockIdx.y, c = blockIdx.x;
    int start = g_cls_off[b * (NCLS + 1) + c];
    int n = g_cls_off[b * (NCLS + 1) + c + 1] - start;
    if (n <= 0 || n <= lo || n > hi) return;

    int NP = 128;
    while (NP < n) NP <<= 1;

    extern __shared__ unsigned long long sm64[];
    unsigned long long* skey = sm64;
    unsigned* sslot = (unsigned*)(skey + NP);
    unsigned char* supp = (unsigned char*)(sslot + NP);
    __shared__ float bb[5];

    for (int i = threadIdx.x; i < NP; i += blockDim.x) {
        if (i < n) {
            int item = g_order[b * NSEL + start + i];
            unsigned vb = __float_as_uint(g_val[b * NSEL + item]);
            unsigned fl = g_flat[b * NSEL + item];
            skey[i] = ((unsigned long long)vb << 32) | (unsigned long long)(~fl);
            sslot[i] = (unsigned)item;
        } else {
            skey[i] = 0ull;
            sslot[i] = 0u;
        }
        supp[i] = 0;
    }
    __syncthreads();
    bitonic_desc(skey, sslot, NP);

    for (int i = 0; i < n; i++) {
        __syncthreads();
        if (supp[i]) continue;   // uniform branch: supp is shared
        if (threadIdx.x == 0) {
            unsigned pos = atomicAdd(&g_surv_cnt[b], 1u);
            if (pos < NSEL) {
                g_surv_key[b * NSEL + pos] = skey[i];
                g_surv_slot[b * NSEL + pos] = sslot[i];
            }
            int o = b * NSEL + (int)sslot[i];
            bb[0] = g_nb0[o]; bb[1] = g_nb1[o]; bb[2] = g_nb2[o]; bb[3] = g_nb3[o]; bb[4] = g_area[o];
        }
        __syncthreads();
        float b0 = bb[0], b1 = bb[1], b2 = bb[2], b3 = bb[3], ba = bb[4];
        for (int j = i + 1 + threadIdx.x; j < n; j += blockDim.x) {
            if (!supp[j]) {
                int o = b * NSEL + (int)sslot[j];
                float yy1 = fmaxf(g_nb0[o], b0);
                float xx1 = fmaxf(g_nb1[o], b1);
                float yy2 = fminf(g_nb2[o], b2);
                float xx2 = fminf(g_nb3[o], b3);
                float ih = fmaxf(yy2 - yy1, 0.0f);
                float iw = fmaxf(xx2 - xx1, 0.0f);
                float inter = ih * iw;
                float iou = inter / (g_area[o] + ba - inter + 1e-8f);
                if (iou > 0.5f) supp[j] = 1;
            }
        }
    }
}

// ---------------- pass 5: global sort of survivors + emit top-100 ----------------
__global__ void k_final(const float* __restrict__ scales, float* __restrict__ out) {
    int b = blockIdx.x;
    int tid = threadIdx.x;
    unsigned cnt = min(g_surv_cnt[b], (unsigned)NSEL);
    int NP = 256;
    while (NP < (int)cnt) NP <<= 1;

    extern __shared__ unsigned long long sm64[];
    unsigned long long* skey = sm64;
    unsigned* sslot = (unsigned*)(skey + NP);

    for (int i = tid; i < NP; i += blockDim.x) {
        if (i < (int)cnt) {
            skey[i] = g_surv_key[b * NSEL + i];
            sslot[i] = g_surv_slot[b * NSEL + i];
        } else {
            skey[i] = 0ull;
            sslot[i] = 0u;
        }
    }
    __syncthreads();
    bitonic_desc(skey, sslot, NP);

    if (tid < NDET) {
        float row[6] = {0.f, 0.f, 0.f, 0.f, 0.f, 0.f};
        if (tid < (int)cnt) {
            int o = b * NSEL + (int)sslot[tid];
            float sc = scales[b];
            row[0] = g_ob0[o] * sc;
            row[1] = g_ob1[o] * sc;
            row[2] = g_ob2[o] * sc;
            row[3] = g_ob3[o] * sc;
            row[4] = g_score[o];
            row[5] = (float)(g_clsid[o] + 1u);
        }
#pragma unroll
        for (int j = 0; j < 6; j++) out[b * (NDET * 6) + tid * 6 + j] = row[j];
    }
}

// ---------------- host ----------------
extern "C" void kernel_launch(void* const* d_in, const int* in_sizes, int n_in,
                              void* d_out, int out_size) {
    // Identify inputs BY ELEMENT COUNT (all 12 counts are unique) — robust to
    // any metadata ordering (setup_inputs interleaves cls/box per level).
    static const long long CLSN[5] = {53084160LL, 13271040LL, 3317760LL, 829440LL, 207360LL};
    static const long long BOXN[5] = {2359296LL, 589824LL, 147456LL, 36864LL, 9216LL};
    const float* cls[5] = {0, 0, 0, 0, 0};
    const float* box[5] = {0, 0, 0, 0, 0};
    const float* anchors = 0;
    const float* scales = 0;
    for (int i = 0; i < n_in; i++) {
        long long s = in_sizes[i];
        const float* p = (const float*)d_in[i];
        for (int l = 0; l < 5; l++) {
            if (s == CLSN[l]) cls[l] = p;
            if (s == BOXN[l]) box[l] = p;
        }
        if (s == 196416LL) anchors = p;
        if (s == 16LL) scales = p;
    }
    float* out = (float*)d_out;

    const int NMS_BIG_SM = 8192 * 13 + 128;   // 8192*(8+4+1)
    const int NMS_SMALL_SM = 512 * 13 + 128;
    const int FIN_SM = 8192 * 12;
    cudaFuncSetAttribute(k_nms, cudaFuncAttributeMaxDynamicSharedMemorySize, NMS_BIG_SM);
    cudaFuncSetAttribute(k_final, cudaFuncAttributeMaxDynamicSharedMemorySize, FIN_SM);

    k_init<<<dim3((BATCH * NCLS + 255) / 256), 256>>>();

    const int HW2[5] = {4096, 1024, 256, 64, 16};
    const int OFF[5] = {0, 36864, 46080, 48384, 48960};
    for (int li = 0; li < 5; li++) {
        int elems = 810 * HW2[li];
        int gx = (elems + 1023) / 1024;  // 256 threads * 4 floats
        k_compact<<<dim3(gx, BATCH), 256>>>(cls[li], HW2[li], OFF[li], elems);
    }

    k_select<<<BATCH, 1024>>>(box[0], box[1], box[2], box[3], box[4], anchors);
    k_bucket<<<BATCH, 128>>>();
    k_nms<<<dim3(NCLS, BATCH), 128, NMS_SMALL_SM>>>(0, 512);
    k_nms<<<dim3(NCLS, BATCH), 128, NMS_BIG_SM>>>(512, NSEL);
    k_final<<<BATCH, 256, FIN_SM>>>(scales, out);
}